// round 4
// baseline (speedup 1.0000x reference)
#include <cuda_runtime.h>

#define BB 16
#define TT 2048
#define CC 200
#define HH 64

// Scratch (device globals; no allocation allowed)
__device__ int   g_idx[BB*TT];
__device__ int   g_cnt[BB];
__device__ float g_q[BB*TT*HH];
__device__ float g_k[BB*TT*HH];
__device__ float g_v[BB*TT*HH];

// ---------------------------------------------------------------------------
// Zero the output (masked query rows must be exactly 0; out is poisoned).
// ---------------------------------------------------------------------------
__global__ void zero_kernel(float4* __restrict__ out, int n4) {
    int i = blockIdx.x * blockDim.x + threadIdx.x;
    int stride = gridDim.x * blockDim.x;
    float4 z = make_float4(0.f, 0.f, 0.f, 0.f);
    for (; i < n4; i += stride) out[i] = z;
}

// ---------------------------------------------------------------------------
// Per-batch ordered compaction of valid (mask != 0) positions.
// One block per batch, 256 threads, 8 positions each, block prefix sum.
// Deterministic (no atomics).
// ---------------------------------------------------------------------------
__global__ void compact_kernel(const int* __restrict__ mask) {
    int b = blockIdx.x;
    const int* m = mask + b * TT;
    __shared__ int s[256];
    int tid = threadIdx.x;
    int base = tid * 8;
    int lm[8];
    int cnt = 0;
#pragma unroll
    for (int i = 0; i < 8; i++) { lm[i] = m[base + i]; cnt += (lm[i] != 0); }
    s[tid] = cnt;
    __syncthreads();
    // Hillis-Steele inclusive scan
    for (int off = 1; off < 256; off <<= 1) {
        int v = (tid >= off) ? s[tid - off] : 0;
        __syncthreads();
        s[tid] += v;
        __syncthreads();
    }
    int pos = s[tid] - cnt;  // exclusive prefix
#pragma unroll
    for (int i = 0; i < 8; i++)
        if (lm[i] != 0) g_idx[b * TT + pos++] = base + i;
    if (tid == 255) g_cnt[b] = s[255];
}

// ---------------------------------------------------------------------------
// Fused K/Q/V projection for valid rows only.
// Block: 192 threads = 3 groups of 64 (one per weight matrix), 16 rows/block.
// x tile staged in smem; 16 fp32 accumulators per thread; float2 smem reads.
// ---------------------------------------------------------------------------
__global__ void proj_kernel(const float* __restrict__ x,
                            const float* __restrict__ Wk,
                            const float* __restrict__ Wq,
                            const float* __restrict__ Wv) {
    int b = blockIdx.y;
    int nv = g_cnt[b];
    int row0 = blockIdx.x * 16;
    if (row0 >= nv) return;

    __shared__ float xs[16][CC];
    __shared__ int   sidx[16];
    int tid = threadIdx.x;

    if (tid < 16) {
        int rg = row0 + tid;
        sidx[tid] = (rg < nv) ? g_idx[b * TT + rg] : -1;
    }
    __syncthreads();

    for (int i = tid; i < 16 * CC; i += 192) {
        int r = i / CC;
        int c = i - r * CC;
        int src = sidx[r];
        xs[r][c] = (src >= 0) ? x[(b * TT + src) * CC + c] : 0.f;
    }
    __syncthreads();

    const float* W;
    float* dst;
    if (tid < 64)        { W = Wk; dst = g_k; }
    else if (tid < 128)  { W = Wq; dst = g_q; }
    else                 { W = Wv; dst = g_v; }
    int h = tid & 63;

    float acc[16];
#pragma unroll
    for (int r = 0; r < 16; r++) acc[r] = 0.f;

#pragma unroll 2
    for (int c = 0; c < CC; c += 2) {
        float w0 = W[c * HH + h];
        float w1 = W[(c + 1) * HH + h];
#pragma unroll
        for (int r = 0; r < 16; r++) {
            float2 xv = *(const float2*)&xs[r][c];
            acc[r] = fmaf(xv.x, w0, acc[r]);
            acc[r] = fmaf(xv.y, w1, acc[r]);
        }
    }

#pragma unroll
    for (int r = 0; r < 16; r++) {
        int rg = row0 + r;
        if (rg < nv) dst[(b * TT + rg) * HH + h] = acc[r];
    }
}

// ---------------------------------------------------------------------------
// Flash attention over compacted K/V.
// Block: 128 threads (16 tx x 8 ty), tile 64 queries x 64 keys.
// Thread register tile: 8 query rows x 4 key cols (S) / 4 head cols (O).
// Smem pitch 65 floats to keep conflicts <= 2-way.
// ---------------------------------------------------------------------------
__global__ __launch_bounds__(128)
void attn_kernel(float* __restrict__ out) {
    extern __shared__ float sm[];
    float* Qs = sm;             // [64][65]
    float* Ks = sm + 64 * 65;   // [64][65]
    float* Vs = sm + 2 * 64 * 65;
    float* Ps = sm + 3 * 64 * 65;

    int b = blockIdx.y;
    int nv = g_cnt[b];
    int q0 = blockIdx.x * 64;
    if (q0 >= nv) return;

    int tid = threadIdx.x;
    int tx = tid & 15;   // key / head subtile
    int ty = tid >> 4;   // query subtile (0..7)

    const float* qb = g_q + b * TT * HH;
    const float* kb = g_k + b * TT * HH;
    const float* vb = g_v + b * TT * HH;

    // Load Q tile (pre-scaled by 1/sqrt(H) = 0.125)
    for (int i = tid; i < 64 * 64; i += 128) {
        int r = i >> 6, h = i & 63;
        Qs[r * 65 + h] = (q0 + r < nv) ? qb[(q0 + r) * HH + h] * 0.125f : 0.f;
    }

    float m[8], l[8], O[8][4];
#pragma unroll
    for (int i = 0; i < 8; i++) {
        m[i] = -1e30f; l[i] = 0.f;
#pragma unroll
        for (int j = 0; j < 4; j++) O[i][j] = 0.f;
    }
    __syncthreads();

    for (int k0 = 0; k0 < nv; k0 += 64) {
        // Stage K/V tiles
        for (int i = tid; i < 64 * 64; i += 128) {
            int r = i >> 6, h = i & 63;
            bool v = (k0 + r) < nv;
            Ks[r * 65 + h] = v ? kb[(k0 + r) * HH + h] : 0.f;
            Vs[r * 65 + h] = v ? vb[(k0 + r) * HH + h] : 0.f;
        }
        __syncthreads();

        // S = Q @ K^T  (8x4 per thread)
        float S[8][4];
#pragma unroll
        for (int i = 0; i < 8; i++)
#pragma unroll
            for (int j = 0; j < 4; j++) S[i][j] = 0.f;

#pragma unroll 4
        for (int h = 0; h < 64; h++) {
            float kv[4], qv[8];
#pragma unroll
            for (int j = 0; j < 4; j++) kv[j] = Ks[(4 * tx + j) * 65 + h];
#pragma unroll
            for (int i = 0; i < 8; i++) qv[i] = Qs[(8 * ty + i) * 65 + h];
#pragma unroll
            for (int i = 0; i < 8; i++)
#pragma unroll
                for (int j = 0; j < 4; j++) S[i][j] = fmaf(qv[i], kv[j], S[i][j]);
        }

        // Mask tail keys of last (partial) tile
        if (k0 + 64 > nv) {
#pragma unroll
            for (int j = 0; j < 4; j++)
                if (k0 + 4 * tx + j >= nv) {
#pragma unroll
                    for (int i = 0; i < 8; i++) S[i][j] = -1e30f;
                }
        }

        // Online softmax update (row reductions across the 16 tx lanes)
#pragma unroll
        for (int i = 0; i < 8; i++) {
            float mt = fmaxf(fmaxf(S[i][0], S[i][1]), fmaxf(S[i][2], S[i][3]));
#pragma unroll
            for (int off = 1; off < 16; off <<= 1)
                mt = fmaxf(mt, __shfl_xor_sync(0xffffffffu, mt, off));
            float mn = fmaxf(m[i], mt);
            float alpha = __expf(m[i] - mn);
            m[i] = mn;
            float ps = 0.f;
#pragma unroll
            for (int j = 0; j < 4; j++) {
                float p = __expf(S[i][j] - mn);
                S[i][j] = p;
                ps += p;
            }
#pragma unroll
            for (int off = 1; off < 16; off <<= 1)
                ps += __shfl_xor_sync(0xffffffffu, ps, off);
            l[i] = l[i] * alpha + ps;
#pragma unroll
            for (int j = 0; j < 4; j++) O[i][j] *= alpha;
        }

        // Publish P tile to smem for the PV GEMM (keys span tx lanes)
#pragma unroll
        for (int i = 0; i < 8; i++)
#pragma unroll
            for (int j = 0; j < 4; j++)
                Ps[(8 * ty + i) * 65 + 4 * tx + j] = S[i][j];
        __syncthreads();

        // O += P @ V   (tx now indexes head dim)
#pragma unroll 4
        for (int kk = 0; kk < 64; kk++) {
            float vv[4], pv[8];
#pragma unroll
            for (int j = 0; j < 4; j++) vv[j] = Vs[kk * 65 + 4 * tx + j];
#pragma unroll
            for (int i = 0; i < 8; i++) pv[i] = Ps[(8 * ty + i) * 65 + kk];
#pragma unroll
            for (int i = 0; i < 8; i++)
#pragma unroll
                for (int j = 0; j < 4; j++) O[i][j] = fmaf(pv[i], vv[j], O[i][j]);
        }
        __syncthreads();
    }

    // Normalize and scatter back to original rows
#pragma unroll
    for (int i = 0; i < 8; i++) {
        int rg = q0 + 8 * ty + i;
        if (rg < nv) {
            int orow = g_idx[b * TT + rg];
            float inv = 1.f / l[i];
            float4 o;
            o.x = O[i][0] * inv;
            o.y = O[i][1] * inv;
            o.z = O[i][2] * inv;
            o.w = O[i][3] * inv;
            *(float4*)&out[(b * TT + orow) * HH + 4 * tx] = o;
        }
    }
}

// ---------------------------------------------------------------------------
extern "C" void kernel_launch(void* const* d_in, const int* in_sizes, int n_in,
                              void* d_out, int out_size) {
    const float* x    = (const float*)d_in[0];
    const int*   mask = (const int*)d_in[1];
    const float* Wk   = (const float*)d_in[2];
    const float* Wq   = (const float*)d_in[3];
    const float* Wv   = (const float*)d_in[4];
    float* out = (float*)d_out;

    const int attn_smem = 4 * 64 * 65 * (int)sizeof(float);  // 66560 B
    cudaFuncSetAttribute(attn_kernel,
                         cudaFuncAttributeMaxDynamicSharedMemorySize, attn_smem);

    zero_kernel<<<512, 256>>>((float4*)out, out_size / 4);
    compact_kernel<<<BB, 256>>>(mask);
    proj_kernel<<<dim3(TT / 16, BB), 192>>>(x, Wk, Wq, Wv);
    attn_kernel<<<dim3(TT / 64, BB), 128, attn_smem>>>(out);
}